// round 5
// baseline (speedup 1.0000x reference)
#include <cuda_runtime.h>
#include <stdint.h>

#define EE     100000
#define DIN    192
#define KNB    8

// ---------------- scratch (device globals) ----------------
__device__ float g_qkv[EE * DIN];   // [E,192] = [q|k|v]
__device__ float g_att[EE * 64];    // [E,64]
__device__ float g_ef1[EE * 64];    // [E,64] layer-1 out

// ---------------- helpers ----------------
__device__ __forceinline__ uint32_t f2tf(float x) {
    uint32_t u; asm("cvt.rna.tf32.f32 %0, %1;" : "=r"(u) : "f"(x)); return u;
}
__device__ __forceinline__ void mma8(float* c, const uint32_t* a, uint32_t b0, uint32_t b1) {
    asm volatile("mma.sync.aligned.m16n8k8.row.col.f32.tf32.tf32.f32 "
        "{%0,%1,%2,%3}, {%4,%5,%6,%7}, {%8,%9}, {%0,%1,%2,%3};"
        : "+f"(c[0]), "+f"(c[1]), "+f"(c[2]), "+f"(c[3])
        : "r"(a[0]), "r"(a[1]), "r"(a[2]), "r"(a[3]), "r"(b0), "r"(b1));
}
__device__ __forceinline__ void ldsm4(uint32_t* f, uint32_t addr) {
    asm volatile("ldmatrix.sync.aligned.m8n8.x4.shared.b16 {%0,%1,%2,%3}, [%4];"
        : "=r"(f[0]), "=r"(f[1]), "=r"(f[2]), "=r"(f[3]) : "r"(addr));
}

// ---------------- QKV smem geometry ----------------
// B tile: [k=32][n=192] stride 200 (frag banks 8*t4+g -> conflict-free), double buf
// A tile: [m=128][k=32] stride 36, double buf
#define BSTRIDE    200
#define B_WORDS_T  (32 * BSTRIDE)       // 6400
#define A_WORDS    (128 * 36)           // 4608
#define QKV_SMEM_BYTES ((2 * B_WORDS_T + 2 * A_WORDS) * 4)   // 88064

// Wo kernel smem
#define WA_WORDS   (128 * 36)
#define WB_WORDS   (64 * 36)
#define WO_SMEM_BYTES ((2 * WA_WORDS + 2 * WB_WORDS) * 4)

// ======================================================================
// Fused QKV GEMM: qkv[E,192] = concat(ef|ef1, nf[src], nf[dst]) @ [Wq|Wk|Wv]
// BM=128, BN=192, BK=32; 512 threads, 16 warps as 4M x 4N, warp tile 32x48.
// ======================================================================
__global__ __launch_bounds__(512, 1) void qkv_mma_kernel(
    const float* __restrict__ ef, const float* __restrict__ nf,
    const int* __restrict__ ei,
    const float* __restrict__ wq, const float* __restrict__ wk, const float* __restrict__ wv,
    int use_ef1)
{
    extern __shared__ uint32_t smem[];
    uint32_t* Bs = smem;                   // [2][32*200]
    uint32_t* As = smem + 2 * B_WORDS_T;   // [2][128*36]

    const int tid = threadIdx.x;
    const int m0  = blockIdx.x * 128;
    const float* efsrc = use_ef1 ? (const float*)g_ef1 : ef;

    // ---- A loader: 512 threads, 4 per row; thread -> (row r, 8-col chunk kb) ----
    const int r  = tid >> 2;
    const int e  = m0 + r;
    const int kb = (tid & 3) * 8;
    const bool valid = (e < EE);
    int si = 0, di = 0;
    if (valid) { si = ei[e]; di = ei[EE + e]; }

    const int wid = tid >> 5, lane = tid & 31;
    const int wm = (wid & 3) * 32, wn = (wid >> 2) * 48;
    const int g = lane >> 2, t4 = lane & 3;
    const int j8 = lane & 7, grp = lane >> 3;

    // ---- ldmatrix A base addresses ----
    const uint32_t As_b = (uint32_t)__cvta_generic_to_shared(As);
    uint32_t aAddr[2];
    #pragma unroll
    for (int mt = 0; mt < 2; mt++) {
        int row = wm + mt * 16 + (grp & 1) * 8 + j8;
        int col = (grp >> 1) * 4;
        aAddr[mt] = As_b + (row * 36 + col) * 4;
    }

    float acc[2][6][4];
    #pragma unroll
    for (int i = 0; i < 2; i++)
        #pragma unroll
        for (int j = 0; j < 6; j++)
            #pragma unroll
            for (int q = 0; q < 4; q++) acc[i][j][q] = 0.f;

    float4 av[2];     // A stage: 2 float4 per thread
    float4 bvv[3];    // B stage: 3 float4 per thread

    auto ldg_tile = [&](int it) {
        const int k0 = it * 32;
        // A
        if (valid) {
            const int reg = k0 >> 6;
            const float* base = (reg == 0) ? efsrc + (size_t)e * 64
                              : (reg == 1) ? nf + (size_t)si * 64
                                           : nf + (size_t)di * 64;
            const int cb = (k0 & 32) + kb;
            av[0] = *reinterpret_cast<const float4*>(base + cb);
            av[1] = *reinterpret_cast<const float4*>(base + cb + 4);
        } else {
            av[0] = make_float4(0.f, 0.f, 0.f, 0.f);
            av[1] = av[0];
        }
        // B tile rows k0..k0+31, all 192 cols; 1536 float4 over 512 threads
        #pragma unroll
        for (int i2 = 0; i2 < 3; i2++) {
            int f = i2 * 512 + tid;
            int kk = f / 48;             // 0..31
            int n4 = (f % 48) * 4;       // 0..188
            const float* W = (n4 < 64) ? wq : (n4 < 128) ? wk : wv;
            bvv[i2] = *reinterpret_cast<const float4*>(W + (size_t)(k0 + kk) * 64 + (n4 & 63));
        }
    };
    auto sts_tile = [&](int b) {
        uint32_t* Aw = As + b * A_WORDS;
        uint32_t* Bw = Bs + b * B_WORDS_T;
        #pragma unroll
        for (int c = 0; c < 2; c++) {
            uint4 u = make_uint4(f2tf(av[c].x), f2tf(av[c].y), f2tf(av[c].z), f2tf(av[c].w));
            *reinterpret_cast<uint4*>(&Aw[r * 36 + kb + c * 4]) = u;
        }
        #pragma unroll
        for (int i2 = 0; i2 < 3; i2++) {
            int f = i2 * 512 + tid;
            int kk = f / 48;
            int n4 = (f % 48) * 4;
            uint32_t* dst = Bw + kk * BSTRIDE + n4;
            dst[0] = f2tf(bvv[i2].x); dst[1] = f2tf(bvv[i2].y);
            dst[2] = f2tf(bvv[i2].z); dst[3] = f2tf(bvv[i2].w);
        }
    };

    const int NIT = DIN / 32;   // 6
    ldg_tile(0);
    sts_tile(0);
    ldg_tile(1);
    __syncthreads();

    for (int i = 0; i < NIT; i++) {
        const int cur = i & 1;
        const uint32_t aOff = cur * (A_WORDS * 4);
        const uint32_t* Bw = Bs + cur * B_WORDS_T + wn + g;
        #pragma unroll
        for (int ks = 0; ks < 4; ks++) {
            const int kl = ks * 8 + t4;
            uint32_t af[2][4];
            ldsm4(af[0], aAddr[0] + aOff + ks * 32);
            ldsm4(af[1], aAddr[1] + aOff + ks * 32);
            uint32_t b0[6], b1[6];
            #pragma unroll
            for (int nt = 0; nt < 6; nt++) {
                b0[nt] = Bw[kl * BSTRIDE + nt * 8];
                b1[nt] = Bw[(kl + 4) * BSTRIDE + nt * 8];
            }
            #pragma unroll
            for (int nt = 0; nt < 6; nt++) {
                mma8(acc[0][nt], af[0], b0[nt], b1[nt]);
                mma8(acc[1][nt], af[1], b0[nt], b1[nt]);
            }
        }
        if (i + 1 < NIT) {
            sts_tile(cur ^ 1);              // regs hold tile i+1
            if (i + 2 < NIT) ldg_tile(i + 2);
            __syncthreads();
        }
    }

    // ---- epilogue ----
    #pragma unroll
    for (int mt = 0; mt < 2; mt++) {
        const int row = m0 + wm + mt * 16 + g;
        #pragma unroll
        for (int nt = 0; nt < 6; nt++) {
            const int col = wn + nt * 8 + t4 * 2;
            if (row < EE)
                *reinterpret_cast<float2*>(g_qkv + (size_t)row * DIN + col) =
                    make_float2(acc[mt][nt][0], acc[mt][nt][1]);
            if (row + 8 < EE)
                *reinterpret_cast<float2*>(g_qkv + (size_t)(row + 8) * DIN + col) =
                    make_float2(acc[mt][nt][2], acc[mt][nt][3]);
        }
    }
}

// ======================================================================
// Wo GEMM + residual: out = ef_in + g_att[E,64] @ Wo[64,64]
// ======================================================================
__global__ __launch_bounds__(256, 2) void wo_mma_kernel(
    const float* __restrict__ Wo,
    const float* __restrict__ ef_ext, float* __restrict__ out_ext,
    int use_ef1_in, int write_ef1)
{
    extern __shared__ uint32_t smem[];
    uint32_t* As = smem;
    uint32_t* Bs = smem + 2 * WA_WORDS;

    const int tid = threadIdx.x;
    const int m0  = blockIdx.x * 128;
    const float* ef_in = use_ef1_in ? (const float*)g_ef1 : ef_ext;
    float* out = write_ef1 ? (float*)g_ef1 : out_ext;

    const int r  = tid >> 1;
    const int e  = m0 + r;
    const int kb = (tid & 1) * 16;
    const bool valid = (e < EE);

    const int bk = tid & 31;
    const int bn = (tid >> 5) * 8;

    const int wid = tid >> 5, lane = tid & 31;
    const int wm = (wid & 3) * 32, wn = (wid >> 2) * 32;
    const int g = lane >> 2, t4 = lane & 3;
    const int j8 = lane & 7, grp = lane >> 3;

    const uint32_t As_b = (uint32_t)__cvta_generic_to_shared(As);
    const uint32_t Bs_b = (uint32_t)__cvta_generic_to_shared(Bs);
    uint32_t aAddr[2], bAddr[2];
    #pragma unroll
    for (int mt = 0; mt < 2; mt++) {
        int row = wm + mt * 16 + (grp & 1) * 8 + j8;
        int col = (grp >> 1) * 4;
        aAddr[mt] = As_b + (row * 36 + col) * 4;
    }
    #pragma unroll
    for (int p = 0; p < 2; p++) {
        int row = wn + p * 16 + (grp >> 1) * 8 + j8;
        int col = (grp & 1) * 4;
        bAddr[p] = Bs_b + (row * 36 + col) * 4;
    }

    float acc[2][4][4];
    #pragma unroll
    for (int i = 0; i < 2; i++)
        #pragma unroll
        for (int j = 0; j < 4; j++)
            #pragma unroll
            for (int q = 0; q < 4; q++) acc[i][j][q] = 0.f;

    float4 av[4], bv[2];
    auto ldg_tile = [&](int it) {
        const int k0 = it * 32;
        if (valid) {
            const float* base = g_att + (size_t)e * 64 + k0 + kb;
            #pragma unroll
            for (int c = 0; c < 4; c++) av[c] = *reinterpret_cast<const float4*>(base + c * 4);
        } else {
            #pragma unroll
            for (int c = 0; c < 4; c++) av[c] = make_float4(0.f, 0.f, 0.f, 0.f);
        }
        #pragma unroll
        for (int c = 0; c < 2; c++)
            bv[c] = *reinterpret_cast<const float4*>(Wo + (size_t)(k0 + bk) * 64 + bn + c * 4);
    };
    auto sts_tile = [&](int b) {
        uint32_t* Aw = As + b * WA_WORDS;
        uint32_t* Bw = Bs + b * WB_WORDS;
        #pragma unroll
        for (int c = 0; c < 4; c++) {
            uint4 u = make_uint4(f2tf(av[c].x), f2tf(av[c].y), f2tf(av[c].z), f2tf(av[c].w));
            *reinterpret_cast<uint4*>(&Aw[r * 36 + kb + c * 4]) = u;
        }
        #pragma unroll
        for (int c = 0; c < 2; c++) {
            float vv[4] = {bv[c].x, bv[c].y, bv[c].z, bv[c].w};
            #pragma unroll
            for (int j = 0; j < 4; j++) Bw[(bn + c * 4 + j) * 36 + bk] = f2tf(vv[j]);
        }
    };

    ldg_tile(0);
    sts_tile(0);
    ldg_tile(1);
    __syncthreads();

    #pragma unroll
    for (int i = 0; i < 2; i++) {
        const int cur = i & 1;
        const uint32_t aOff = cur * (WA_WORDS * 4);
        const uint32_t bOff = cur * (WB_WORDS * 4);
        #pragma unroll
        for (int ks = 0; ks < 4; ks++) {
            uint32_t af0[4], af1[4], bf0[4], bf1[4];
            ldsm4(af0, aAddr[0] + aOff + ks * 32);
            ldsm4(af1, aAddr[1] + aOff + ks * 32);
            ldsm4(bf0, bAddr[0] + bOff + ks * 32);
            ldsm4(bf1, bAddr[1] + bOff + ks * 32);
            mma8(acc[0][0], af0, bf0[0], bf0[1]);
            mma8(acc[0][1], af0, bf0[2], bf0[3]);
            mma8(acc[0][2], af0, bf1[0], bf1[1]);
            mma8(acc[0][3], af0, bf1[2], bf1[3]);
            mma8(acc[1][0], af1, bf0[0], bf0[1]);
            mma8(acc[1][1], af1, bf0[2], bf0[3]);
            mma8(acc[1][2], af1, bf1[0], bf1[1]);
            mma8(acc[1][3], af1, bf1[2], bf1[3]);
        }
        if (i == 0) {
            sts_tile(1);
            __syncthreads();
        }
    }

    #pragma unroll
    for (int mt = 0; mt < 2; mt++) {
        const int row = m0 + wm + mt * 16 + g;
        #pragma unroll
        for (int nt = 0; nt < 4; nt++) {
            const int col = wn + nt * 8 + t4 * 2;
            if (row < EE) {
                float2 rr = *reinterpret_cast<const float2*>(ef_in + (size_t)row * 64 + col);
                *reinterpret_cast<float2*>(out + (size_t)row * 64 + col) =
                    make_float2(rr.x + acc[mt][nt][0], rr.y + acc[mt][nt][1]);
            }
            if (row + 8 < EE) {
                float2 rr = *reinterpret_cast<const float2*>(ef_in + (size_t)(row + 8) * 64 + col);
                *reinterpret_cast<float2*>(out + (size_t)(row + 8) * 64 + col) =
                    make_float2(rr.x + acc[mt][nt][2], rr.y + acc[mt][nt][3]);
            }
        }
    }
}

// ---------------- attention: one warp per dst edge ----------------
__global__ void attn_kernel(const int* __restrict__ adj_src) {
    int gw = (blockIdx.x * blockDim.x + threadIdx.x) >> 5;
    int lane = threadIdx.x & 31;
    if (gw >= EE) return;

    const float* qrow = g_qkv + (size_t)gw * DIN;
    float2 q = *reinterpret_cast<const float2*>(qrow + 2 * lane);

    float sj[KNB], v0[KNB], v1[KNB];
    int base = gw * KNB;
    #pragma unroll
    for (int j = 0; j < KNB; j++) {
        int n = adj_src[base + j];
        const float* kr = g_qkv + (size_t)n * DIN + 64;
        float2 kk = *reinterpret_cast<const float2*>(kr + 2 * lane);
        float2 vv = *reinterpret_cast<const float2*>(kr + 64 + 2 * lane);
        float p = q.x * kk.x + q.y * kk.y;
        p += __shfl_xor_sync(0xffffffffu, p, 1);
        p += __shfl_xor_sync(0xffffffffu, p, 2);
        p += __shfl_xor_sync(0xffffffffu, p, 4);
        sj[j] = p * 0.25f;
        v0[j] = vv.x;
        v1[j] = vv.y;
    }

    float m = sj[0];
    #pragma unroll
    for (int j = 1; j < KNB; j++) m = fmaxf(m, sj[j]);

    float denom = 0.f, a0 = 0.f, a1 = 0.f;
    #pragma unroll
    for (int j = 0; j < KNB; j++) {
        float w = __expf(sj[j] - m);
        denom += w;
        a0 += w * v0[j];
        a1 += w * v1[j];
    }
    float inv = 1.0f / denom;
    *reinterpret_cast<float2*>(g_att + (size_t)gw * 64 + 2 * lane) =
        make_float2(a0 * inv, a1 * inv);
}

// ---------------- launch ----------------
extern "C" void kernel_launch(void* const* d_in, const int* in_sizes, int n_in,
                              void* d_out, int out_size) {
    const float* nf      = (const float*)d_in[0];
    const float* ef      = (const float*)d_in[1];
    const int*   ei      = (const int*)d_in[2];
    const int*   adj_src = (const int*)d_in[4];
    const float* l1_Wq = (const float*)d_in[6];
    const float* l1_Wk = (const float*)d_in[7];
    const float* l1_Wv = (const float*)d_in[8];
    const float* l1_Wo = (const float*)d_in[9];
    const float* l2_Wq = (const float*)d_in[10];
    const float* l2_Wk = (const float*)d_in[11];
    const float* l2_Wv = (const float*)d_in[12];
    const float* l2_Wo = (const float*)d_in[13];
    float* out = (float*)d_out;

    static int attr_done = 0;
    if (!attr_done) {
        cudaFuncSetAttribute(qkv_mma_kernel, cudaFuncAttributeMaxDynamicSharedMemorySize, QKV_SMEM_BYTES);
        cudaFuncSetAttribute(wo_mma_kernel,  cudaFuncAttributeMaxDynamicSharedMemorySize, WO_SMEM_BYTES);
        attr_done = 1;
    }

    const int gq = (EE + 127) / 128;
    const int gwb = (EE + 127) / 128;
    const int attn_blocks = EE / 8;

    // layer 1
    qkv_mma_kernel<<<gq, 512, QKV_SMEM_BYTES>>>(ef, nf, ei, l1_Wq, l1_Wk, l1_Wv, 0);
    attn_kernel<<<attn_blocks, 256>>>(adj_src);
    wo_mma_kernel<<<gwb, 256, WO_SMEM_BYTES>>>(l1_Wo, ef, nullptr, 0, 1);

    // layer 2
    qkv_mma_kernel<<<gq, 512, QKV_SMEM_BYTES>>>(ef, nf, ei, l2_Wq, l2_Wk, l2_Wv, 1);
    attn_kernel<<<attn_blocks, 256>>>(adj_src);
    wo_mma_kernel<<<gwb, 256, WO_SMEM_BYTES>>>(l2_Wo, nullptr, out, 1, 0);
}